// round 6
// baseline (speedup 1.0000x reference)
#include <cuda_runtime.h>
#include <float.h>
#include <math.h>

// x = [B=16, C=2048, H=48, W=64] fp32. 21 regions; 6 row ranges from 6 row
// segments (breakpoints 0,12,16,24,32,36,48).
#define B_  16
#define C_  2048
#define H_  48
#define W_  64
#define NPLANE (B_ * C_)
#define R_  21
#define EPS_ 1e-6f

__device__ float g_vecs[B_ * R_ * C_];      // [b][r][c]
__device__ float g_sumsq[B_ * R_] = {};     // per-(b,r) sum of squares
                                            // (zero at load; agg re-zeroes
                                            //  after use for graph replays)

// RR0=[0,48) RR1=[0,32) RR2=[16,48) RR3=[0,24) RR4=[12,36) RR5=[24,48)
__constant__ int REG_RR[R_] = {
    0,
    0, 0,
    1, 1, 1,
    2, 2, 2,
    3, 3, 3, 3,
    4, 4, 4, 4,
    5, 5, 5, 5
};
__constant__ int REG_C0[R_] = {
    0,
    0, 16,
    0, 16, 32,
    0, 16, 32,
    0, 13, 26, 40,
    0, 13, 26, 40,
    0, 13, 26, 40
};
__constant__ int REG_C1[R_] = {
    64,
    48, 64,
    32, 48, 64,
    32, 48, 64,
    24, 37, 50, 64,
    24, 37, 50, 64,
    24, 37, 50, 64
};

// ---------------------------------------------------------------------------
// Kernel 1 (proven 70.7us config): one block per (b,c) plane, 64 threads =
// one per column. Scalar coalesced LDG.32 column-walk; 6 segment maxes in
// registers; 6 row-range maxes in smem; 21 region column reductions.
// NEW: lane 0 also accumulates m^2 into g_sumsq via L2 atomics (fuses the
// norm-reduction kernel into the memory-bound phase for free).
// ---------------------------------------------------------------------------
__global__ __launch_bounds__(64) void rpool_max_kernel(
    const float* __restrict__ x, float* __restrict__ vecs,
    float* __restrict__ sumsq)
{
    const int plane = blockIdx.x;             // b * C + c
    const float* __restrict__ p = x + (size_t)plane * (H_ * W_);
    const int col = threadIdx.x;              // 0..63

    float s0 = -FLT_MAX, s1 = -FLT_MAX, s2 = -FLT_MAX;
    float s3 = -FLT_MAX, s4 = -FLT_MAX, s5 = -FLT_MAX;

    #pragma unroll
    for (int r = 0; r < 12; r++)  s0 = fmaxf(s0, p[r * W_ + col]);
    #pragma unroll
    for (int r = 12; r < 16; r++) s1 = fmaxf(s1, p[r * W_ + col]);
    #pragma unroll
    for (int r = 16; r < 24; r++) s2 = fmaxf(s2, p[r * W_ + col]);
    #pragma unroll
    for (int r = 24; r < 32; r++) s3 = fmaxf(s3, p[r * W_ + col]);
    #pragma unroll
    for (int r = 32; r < 36; r++) s4 = fmaxf(s4, p[r * W_ + col]);
    #pragma unroll
    for (int r = 36; r < 48; r++) s5 = fmaxf(s5, p[r * W_ + col]);

    __shared__ float rr[6][W_];
    const float m012 = fmaxf(fmaxf(s0, s1), s2);
    const float m345 = fmaxf(fmaxf(s3, s4), s5);
    rr[0][col] = fmaxf(m012, m345);                     // rows [0,48)
    rr[1][col] = fmaxf(m012, s3);                       // rows [0,32)
    rr[2][col] = fmaxf(fmaxf(s2, s3), fmaxf(s4, s5));   // rows [16,48)
    rr[3][col] = m012;                                  // rows [0,24)
    rr[4][col] = fmaxf(fmaxf(s1, s2), fmaxf(s3, s4));   // rows [12,36)
    rr[5][col] = m345;                                  // rows [24,48)
    __syncthreads();

    const int warp = threadIdx.x >> 5;
    const int lane = threadIdx.x & 31;
    const int b = plane >> 11;          // / C_
    const int c = plane & (C_ - 1);     // % C_

    for (int reg = warp; reg < R_; reg += 2) {
        const int ri = REG_RR[reg];
        const int c0 = REG_C0[reg];
        const int c1 = REG_C1[reg];
        float m = -FLT_MAX;
        for (int cc = c0 + lane; cc < c1; cc += 32)
            m = fmaxf(m, rr[ri][cc]);
        #pragma unroll
        for (int o = 16; o > 0; o >>= 1)
            m = fmaxf(m, __shfl_xor_sync(0xffffffffu, m, o));
        if (lane == 0) {
            vecs[((size_t)(b * R_ + reg)) * C_ + c] = m;
            atomicAdd(&sumsq[b * R_ + reg], m * m);   // REDG, 336 addrs
        }
    }
}

// ---------------------------------------------------------------------------
// Kernel 2: aggregate. grid = 16 blocks x 512 threads. Reads the 21
// pre-accumulated sums of squares, builds inverse norms, does the weighted
// region sum + global L2 normalize, stores, then re-zeroes its sumsq slots
// so the next graph replay starts clean.
// ---------------------------------------------------------------------------
__global__ __launch_bounds__(512) void rpool_agg_kernel(
    const float* __restrict__ vecs, float* __restrict__ sumsq,
    float* __restrict__ out)
{
    const int b = blockIdx.x;
    const int tid = threadIdx.x;                // 0..511 -> float4 index
    const int lane = tid & 31, warp = tid >> 5;
    const float4* __restrict__ vb4 =
        reinterpret_cast<const float4*>(vecs + (size_t)b * R_ * C_);

    __shared__ float w[R_];
    if (tid < R_) w[tid] = 1.0f / (sqrtf(sumsq[b * R_ + tid]) + EPS_);
    __syncthreads();

    float4 s = make_float4(0.f, 0.f, 0.f, 0.f);
    #pragma unroll
    for (int r = 0; r < R_; r++) {
        const float4 v = vb4[r * 512 + tid];
        const float k = w[r];
        s.x += v.x * k; s.y += v.y * k;
        s.z += v.z * k; s.w += v.w * k;
    }
    float local = s.x * s.x + s.y * s.y + s.z * s.z + s.w * s.w;

    #pragma unroll
    for (int o = 16; o > 0; o >>= 1)
        local += __shfl_xor_sync(0xffffffffu, local, o);
    __shared__ float ws[16];
    if (lane == 0) ws[warp] = local;
    __syncthreads();
    __shared__ float s_invn;
    if (warp == 0) {
        float t = (lane < 16) ? ws[lane] : 0.f;
        #pragma unroll
        for (int o = 8; o > 0; o >>= 1)
            t += __shfl_xor_sync(0xffffffffu, t, o);
        if (lane == 0) s_invn = 1.0f / (sqrtf(t) + EPS_);
    }
    __syncthreads();

    const float invn = s_invn;
    s.x *= invn; s.y *= invn; s.z *= invn; s.w *= invn;
    reinterpret_cast<float4*>(out)[(size_t)b * 512 + tid] = s;

    // reset accumulators for the next replay (disjoint per block; reads of
    // sumsq happened before the first __syncthreads above)
    if (tid < R_) sumsq[b * R_ + tid] = 0.f;
}

extern "C" void kernel_launch(void* const* d_in, const int* in_sizes, int n_in,
                              void* d_out, int out_size)
{
    const float* x = (const float*)d_in[0];
    float* out = (float*)d_out;

    float* vecs;
    float* sumsq;
    cudaGetSymbolAddress((void**)&vecs, g_vecs);
    cudaGetSymbolAddress((void**)&sumsq, g_sumsq);

    rpool_max_kernel<<<NPLANE, 64>>>(x, vecs, sumsq);
    rpool_agg_kernel<<<B_, 512>>>(vecs, sumsq, out);
}

// round 7
// speedup vs baseline: 5.4148x; 5.4148x over previous
#include <cuda_runtime.h>
#include <float.h>
#include <math.h>

// x = [B=16, C=2048, H=48, W=64] fp32. 21 regions; 6 row ranges from 6 row
// segments (breakpoints 0,12,16,24,32,36,48).
#define B_  16
#define C_  2048
#define H_  48
#define W_  64
#define NPLANE (B_ * C_)
#define R_  21
#define EPS_ 1e-6f

#define POOL_BLOCKS (148 * 32)   // persistent: one wave at 64 thr, 32 CTA/SM

__device__ float g_vecs[B_ * R_ * C_];    // [b][r][c]
__device__ float g_inv[B_ * R_];          // 1/(||v||+eps) per (b,r)

// RR0=[0,48) RR1=[0,32) RR2=[16,48) RR3=[0,24) RR4=[12,36) RR5=[24,48)
__constant__ int REG_RR[R_] = {
    0,
    0, 0,
    1, 1, 1,
    2, 2, 2,
    3, 3, 3, 3,
    4, 4, 4, 4,
    5, 5, 5, 5
};
__constant__ int REG_C0[R_] = {
    0,
    0, 16,
    0, 16, 32,
    0, 16, 32,
    0, 13, 26, 40,
    0, 13, 26, 40,
    0, 13, 26, 40
};
__constant__ int REG_C1[R_] = {
    64,
    48, 64,
    32, 48, 64,
    32, 48, 64,
    24, 37, 50, 64,
    24, 37, 50, 64,
    24, 37, 50, 64
};

// ---------------------------------------------------------------------------
// Kernel 1: persistent pool. 64 threads = one per column; grid-stride loop
// over planes (each block handles ~7 planes) -> single wave, no chip-level
// wave transitions. Per plane: scalar coalesced LDG.32 column-walk, 6 segment
// maxes in registers, 6 row-range maxes in smem, 21 region reductions.
// ---------------------------------------------------------------------------
__global__ __launch_bounds__(64) void rpool_max_kernel(
    const float* __restrict__ x, float* __restrict__ vecs)
{
    const int col = threadIdx.x;              // 0..63
    const int warp = threadIdx.x >> 5;
    const int lane = threadIdx.x & 31;
    __shared__ float rr[6][W_];

    for (int plane = blockIdx.x; plane < NPLANE; plane += POOL_BLOCKS) {
        const float* __restrict__ p = x + (size_t)plane * (H_ * W_);

        float s0 = -FLT_MAX, s1 = -FLT_MAX, s2 = -FLT_MAX;
        float s3 = -FLT_MAX, s4 = -FLT_MAX, s5 = -FLT_MAX;

        #pragma unroll
        for (int r = 0; r < 12; r++)  s0 = fmaxf(s0, p[r * W_ + col]);
        #pragma unroll
        for (int r = 12; r < 16; r++) s1 = fmaxf(s1, p[r * W_ + col]);
        #pragma unroll
        for (int r = 16; r < 24; r++) s2 = fmaxf(s2, p[r * W_ + col]);
        #pragma unroll
        for (int r = 24; r < 32; r++) s3 = fmaxf(s3, p[r * W_ + col]);
        #pragma unroll
        for (int r = 32; r < 36; r++) s4 = fmaxf(s4, p[r * W_ + col]);
        #pragma unroll
        for (int r = 36; r < 48; r++) s5 = fmaxf(s5, p[r * W_ + col]);

        const float m012 = fmaxf(fmaxf(s0, s1), s2);
        const float m345 = fmaxf(fmaxf(s3, s4), s5);
        rr[0][col] = fmaxf(m012, m345);                     // rows [0,48)
        rr[1][col] = fmaxf(m012, s3);                       // rows [0,32)
        rr[2][col] = fmaxf(fmaxf(s2, s3), fmaxf(s4, s5));   // rows [16,48)
        rr[3][col] = m012;                                  // rows [0,24)
        rr[4][col] = fmaxf(fmaxf(s1, s2), fmaxf(s3, s4));   // rows [12,36)
        rr[5][col] = m345;                                  // rows [24,48)
        __syncthreads();

        const int b = plane >> 11;          // / C_
        const int c = plane & (C_ - 1);     // % C_

        for (int reg = warp; reg < R_; reg += 2) {
            const int ri = REG_RR[reg];
            const int c0 = REG_C0[reg];
            const int c1 = REG_C1[reg];
            float m = -FLT_MAX;
            for (int cc = c0 + lane; cc < c1; cc += 32)
                m = fmaxf(m, rr[ri][cc]);
            #pragma unroll
            for (int o = 16; o > 0; o >>= 1)
                m = fmaxf(m, __shfl_xor_sync(0xffffffffu, m, o));
            if (lane == 0)
                vecs[((size_t)(b * R_ + reg)) * C_ + c] = m;
        }
        __syncthreads();   // rr reused next iteration
    }
}

// ---------------------------------------------------------------------------
// Kernel 2: per-(b,r) inverse L2 norm. grid = 336 blocks x 256 threads.
// ---------------------------------------------------------------------------
__global__ __launch_bounds__(256) void rpool_inv_kernel(
    const float* __restrict__ vecs, float* __restrict__ inv)
{
    const int br = blockIdx.x;                  // b * R + r
    const int tid = threadIdx.x;
    const float4* __restrict__ v4 =
        reinterpret_cast<const float4*>(vecs + (size_t)br * C_);

    const float4 a = v4[tid];
    const float4 b = v4[tid + 256];
    float acc = a.x * a.x + a.y * a.y + a.z * a.z + a.w * a.w
              + b.x * b.x + b.y * b.y + b.z * b.z + b.w * b.w;

    #pragma unroll
    for (int o = 16; o > 0; o >>= 1)
        acc += __shfl_xor_sync(0xffffffffu, acc, o);

    __shared__ float ws[8];
    const int lane = tid & 31, warp = tid >> 5;
    if (lane == 0) ws[warp] = acc;
    __syncthreads();
    if (warp == 0) {
        float t = (lane < 8) ? ws[lane] : 0.f;
        #pragma unroll
        for (int o = 4; o > 0; o >>= 1)
            t += __shfl_xor_sync(0xffffffffu, t, o);
        if (lane == 0) inv[br] = 1.0f / (sqrtf(t) + EPS_);
    }
}

// ---------------------------------------------------------------------------
// Kernel 3: aggregate. grid = 16 blocks x 512 threads.
// ---------------------------------------------------------------------------
__global__ __launch_bounds__(512) void rpool_agg_kernel(
    const float* __restrict__ vecs, const float* __restrict__ inv,
    float* __restrict__ out)
{
    const int b = blockIdx.x;
    const int tid = threadIdx.x;                // 0..511 -> float4 index
    const int lane = tid & 31, warp = tid >> 5;
    const float4* __restrict__ vb4 =
        reinterpret_cast<const float4*>(vecs + (size_t)b * R_ * C_);

    __shared__ float w[R_];
    if (tid < R_) w[tid] = inv[b * R_ + tid];
    __syncthreads();

    float4 s = make_float4(0.f, 0.f, 0.f, 0.f);
    #pragma unroll
    for (int r = 0; r < R_; r++) {
        const float4 v = vb4[r * 512 + tid];
        const float k = w[r];
        s.x += v.x * k; s.y += v.y * k;
        s.z += v.z * k; s.w += v.w * k;
    }
    float local = s.x * s.x + s.y * s.y + s.z * s.z + s.w * s.w;

    #pragma unroll
    for (int o = 16; o > 0; o >>= 1)
        local += __shfl_xor_sync(0xffffffffu, local, o);
    __shared__ float ws[16];
    if (lane == 0) ws[warp] = local;
    __syncthreads();
    __shared__ float s_invn;
    if (warp == 0) {
        float t = (lane < 16) ? ws[lane] : 0.f;
        #pragma unroll
        for (int o = 8; o > 0; o >>= 1)
            t += __shfl_xor_sync(0xffffffffu, t, o);
        if (lane == 0) s_invn = 1.0f / (sqrtf(t) + EPS_);
    }
    __syncthreads();

    const float invn = s_invn;
    s.x *= invn; s.y *= invn; s.z *= invn; s.w *= invn;
    reinterpret_cast<float4*>(out)[(size_t)b * 512 + tid] = s;
}

extern "C" void kernel_launch(void* const* d_in, const int* in_sizes, int n_in,
                              void* d_out, int out_size)
{
    const float* x = (const float*)d_in[0];
    float* out = (float*)d_out;

    float* vecs;
    float* inv;
    cudaGetSymbolAddress((void**)&vecs, g_vecs);
    cudaGetSymbolAddress((void**)&inv, g_inv);

    rpool_max_kernel<<<POOL_BLOCKS, 64>>>(x, vecs);
    rpool_inv_kernel<<<B_ * R_, 256>>>(vecs, inv);
    rpool_agg_kernel<<<B_, 512>>>(vecs, inv, out);
}

// round 8
// speedup vs baseline: 6.3848x; 1.1791x over previous
#include <cuda_runtime.h>
#include <float.h>
#include <math.h>

// x = [B=16, C=2048, H=48, W=64] fp32. 21 regions; 6 row ranges from 6 row
// segments (breakpoints 0,12,16,24,32,36,48).
#define B_  16
#define C_  2048
#define H_  48
#define W_  64
#define NPLANE (B_ * C_)
#define R_  21
#define EPS_ 1e-6f

__device__ float g_vecs[B_ * R_ * C_];    // [b][r][c]

// RR0=[0,48) RR1=[0,32) RR2=[16,48) RR3=[0,24) RR4=[12,36) RR5=[24,48)
__constant__ int REG_RR[R_] = {
    0,
    0, 0,
    1, 1, 1,
    2, 2, 2,
    3, 3, 3, 3,
    4, 4, 4, 4,
    5, 5, 5, 5
};
__constant__ int REG_C0[R_] = {
    0,
    0, 16,
    0, 16, 32,
    0, 16, 32,
    0, 13, 26, 40,
    0, 13, 26, 40,
    0, 13, 26, 40
};
__constant__ int REG_C1[R_] = {
    64,
    48, 64,
    32, 48, 64,
    32, 48, 64,
    24, 37, 50, 64,
    24, 37, 50, 64,
    24, 37, 50, 64
};

// ---------------------------------------------------------------------------
// Kernel 1 (R4-exact, measured 70.7us / DRAM 73%): one block per (b,c)
// plane, 64 threads = one per column. Scalar coalesced LDG.32 column-walk,
// 6 segment maxes in registers, 6 row-range maxes in smem, 21 region
// column reductions via shuffles.
// ---------------------------------------------------------------------------
__global__ __launch_bounds__(64) void rpool_max_kernel(
    const float* __restrict__ x, float* __restrict__ vecs)
{
    const int plane = blockIdx.x;             // b * C + c
    const float* __restrict__ p = x + (size_t)plane * (H_ * W_);
    const int col = threadIdx.x;              // 0..63

    float s0 = -FLT_MAX, s1 = -FLT_MAX, s2 = -FLT_MAX;
    float s3 = -FLT_MAX, s4 = -FLT_MAX, s5 = -FLT_MAX;

    #pragma unroll
    for (int r = 0; r < 12; r++)  s0 = fmaxf(s0, p[r * W_ + col]);
    #pragma unroll
    for (int r = 12; r < 16; r++) s1 = fmaxf(s1, p[r * W_ + col]);
    #pragma unroll
    for (int r = 16; r < 24; r++) s2 = fmaxf(s2, p[r * W_ + col]);
    #pragma unroll
    for (int r = 24; r < 32; r++) s3 = fmaxf(s3, p[r * W_ + col]);
    #pragma unroll
    for (int r = 32; r < 36; r++) s4 = fmaxf(s4, p[r * W_ + col]);
    #pragma unroll
    for (int r = 36; r < 48; r++) s5 = fmaxf(s5, p[r * W_ + col]);

    __shared__ float rr[6][W_];
    const float m012 = fmaxf(fmaxf(s0, s1), s2);
    const float m345 = fmaxf(fmaxf(s3, s4), s5);
    rr[0][col] = fmaxf(m012, m345);                     // rows [0,48)
    rr[1][col] = fmaxf(m012, s3);                       // rows [0,32)
    rr[2][col] = fmaxf(fmaxf(s2, s3), fmaxf(s4, s5));   // rows [16,48)
    rr[3][col] = m012;                                  // rows [0,24)
    rr[4][col] = fmaxf(fmaxf(s1, s2), fmaxf(s3, s4));   // rows [12,36)
    rr[5][col] = m345;                                  // rows [24,48)
    __syncthreads();

    const int warp = threadIdx.x >> 5;
    const int lane = threadIdx.x & 31;
    const int b = plane >> 11;          // / C_
    const int c = plane & (C_ - 1);     // % C_

    for (int reg = warp; reg < R_; reg += 2) {
        const int ri = REG_RR[reg];
        const int c0 = REG_C0[reg];
        const int c1 = REG_C1[reg];
        float m = -FLT_MAX;
        for (int cc = c0 + lane; cc < c1; cc += 32)
            m = fmaxf(m, rr[ri][cc]);
        #pragma unroll
        for (int o = 16; o > 0; o >>= 1)
            m = fmaxf(m, __shfl_xor_sync(0xffffffffu, m, o));
        if (lane == 0)
            vecs[((size_t)(b * R_ + reg)) * C_ + c] = m;
    }
}

// ---------------------------------------------------------------------------
// Kernel 2 (fused backend): grid = 16 blocks (one per batch) x 672 threads
// (21 warps).
// Pass 1: warp r reduces region r's sum of squares (16 float4 per lane, no
//         block sync inside) -> inv[r] in smem.
// Pass 2: threads 0-511 compute the weighted region sum (21 L2-hot float4
//         loads each), block-reduce the global norm across 21 warps, store.
// ---------------------------------------------------------------------------
__global__ __launch_bounds__(672) void rpool_normagg_kernel(
    const float* __restrict__ vecs, float* __restrict__ out)
{
    const int b = blockIdx.x;
    const int tid = threadIdx.x;
    const int warp = tid >> 5;                 // 0..20
    const int lane = tid & 31;
    const float4* __restrict__ vb4 =
        reinterpret_cast<const float4*>(vecs + (size_t)b * R_ * C_);

    __shared__ float inv[R_];

    // ---- pass 1: warp-per-region L2 norm ----
    {
        const int r = warp;                    // every warp owns one region
        const float4* __restrict__ vr = vb4 + r * 512;
        float acc = 0.f;
        #pragma unroll
        for (int k = 0; k < 16; k++) {
            const float4 v = vr[lane + k * 32];
            acc += v.x * v.x + v.y * v.y + v.z * v.z + v.w * v.w;
        }
        #pragma unroll
        for (int o = 16; o > 0; o >>= 1)
            acc += __shfl_xor_sync(0xffffffffu, acc, o);
        if (lane == 0)
            inv[r] = 1.0f / (sqrtf(acc) + EPS_);
    }
    __syncthreads();

    // ---- pass 2: aggregate + global L2 normalize ----
    float4 s = make_float4(0.f, 0.f, 0.f, 0.f);
    float local = 0.f;
    if (tid < 512) {
        #pragma unroll
        for (int r = 0; r < R_; r++) {
            const float4 v = vb4[r * 512 + tid];
            const float k = inv[r];
            s.x += v.x * k; s.y += v.y * k;
            s.z += v.z * k; s.w += v.w * k;
        }
        local = s.x * s.x + s.y * s.y + s.z * s.z + s.w * s.w;
    }

    #pragma unroll
    for (int o = 16; o > 0; o >>= 1)
        local += __shfl_xor_sync(0xffffffffu, local, o);
    __shared__ float ws[R_];
    if (lane == 0) ws[warp] = local;
    __syncthreads();
    __shared__ float s_invn;
    if (warp == 0) {
        float t = (lane < R_) ? ws[lane] : 0.f;
        #pragma unroll
        for (int o = 16; o > 0; o >>= 1)
            t += __shfl_xor_sync(0xffffffffu, t, o);
        if (lane == 0) s_invn = 1.0f / (sqrtf(t) + EPS_);
    }
    __syncthreads();

    if (tid < 512) {
        const float invn = s_invn;
        s.x *= invn; s.y *= invn; s.z *= invn; s.w *= invn;
        reinterpret_cast<float4*>(out)[(size_t)b * 512 + tid] = s;
    }
}

extern "C" void kernel_launch(void* const* d_in, const int* in_sizes, int n_in,
                              void* d_out, int out_size)
{
    const float* x = (const float*)d_in[0];
    float* out = (float*)d_out;

    float* vecs;
    cudaGetSymbolAddress((void**)&vecs, g_vecs);

    rpool_max_kernel<<<NPLANE, 64>>>(x, vecs);
    rpool_normagg_kernel<<<B_, 672>>>(vecs, out);
}